// round 1
// baseline (speedup 1.0000x reference)
#include <cuda_runtime.h>
#include <math.h>

#define BATCH 8192
#define NHS   64
#define NC    68   // HS + 4 channels

// ---------------- scratch (device globals: no allocation allowed) ----------
__device__ float g_x[BATCH * NHS * 36];            // current x, (B,64,6,6)   75.5 MB
__device__ float g_vec[4 * BATCH * NC * 25];       // conv output vectors     222.8 MB
__device__ float g_mat[4 * BATCH * NHS];           // final matmul result     8.4 MB

__device__ __forceinline__ float sc_act(float v) {
    float s, c;
    sincosf(v, &s, &c);
    return s + c;
}

// ---------------- conv core: accumulate one 3x3 SAME conv -------------------
// Each thread owns one (tile, co) pair and WS*WS accumulators.
// Weights streamed through shared in chunks of 4 input channels.
template<int WS>
__device__ __forceinline__ void conv_accum(
    float acc[WS * WS], const float* __restrict__ wg,
    float* shw, const float* tin, int co, int tid)
{
    constexpr int P = WS * WS;
    for (int chunk = 0; chunk < 17; chunk++) {
        __syncthreads();
        // load w[co][chunk*4 .. chunk*4+3][3][3] for all co into shared
        for (int e = tid; e < NC * 36; e += 272)
            shw[e] = wg[(e / 36) * 612 + chunk * 36 + (e % 36)];
        __syncthreads();
        #pragma unroll
        for (int cil = 0; cil < 4; cil++) {
            const int ci = chunk * 4 + cil;
            float r[P];
            #pragma unroll
            for (int p = 0; p < P; p++) r[p] = tin[ci * P + p];
            float wv[9];
            #pragma unroll
            for (int k = 0; k < 9; k++) wv[k] = shw[(co * 4 + cil) * 9 + k];
            #pragma unroll
            for (int y = 0; y < WS; y++) {
                #pragma unroll
                for (int x = 0; x < WS; x++) {
                    float a = acc[y * WS + x];
                    #pragma unroll
                    for (int ky = 0; ky < 3; ky++) {
                        const int yy = y + ky - 1;
                        if (yy < 0 || yy >= WS) continue;
                        #pragma unroll
                        for (int kx = 0; kx < 3; kx++) {
                            const int xx = x + kx - 1;
                            if (xx < 0 || xx >= WS) continue;
                            a = fmaf(wv[ky * 3 + kx], r[yy * WS + xx], a);
                        }
                    }
                    acc[y * WS + x] = a;
                }
            }
        }
    }
}

// ---------------- fused per-iteration conv pipeline -------------------------
// One CTA = 4 (corner,batch) tiles. 272 threads: tid>>2 = co (0..67), tid&3 = tile slot.
// load(+corner extract)+sincos -> conv1 -> relu -> sincos -> conv3 -> relu -> g_vec
template<int WS, bool FIRST>
__global__ void __launch_bounds__(272) conv_pipe(
    const float* __restrict__ xin,
    const float* __restrict__ cell,
    const float* __restrict__ coord,
    const float* __restrict__ w1, const float* __restrict__ b1,
    const float* __restrict__ w3, const float* __restrict__ b3)
{
    constexpr int P   = WS * WS;
    constexpr int OFF = 6 - WS;
    __shared__ float sh_t[4 * NC * P];
    __shared__ float sh_w[NC * 36];
    const int tid   = threadIdx.x;
    const int tile0 = blockIdx.x * 4;

    // corner-extract + concat(x, cell, coord) + sin+cos into shared
    for (int e = tid; e < 4 * NC * P; e += 272) {
        const int slot = e / (NC * P);
        const int rr   = e % (NC * P);
        const int ch   = rr / P, p = rr % P;
        const int y    = p / WS, xp = p % WS;
        const int tile = tile0 + slot;
        const int c    = tile >> 13, b = tile & (BATCH - 1);
        const int Y    = y + (c >> 1) * OFF, X = xp + (c & 1) * OFF;
        float v;
        if (ch < NHS)
            v = FIRST ? xin[((b * NHS + ch) * 6 + Y) * 6 + X]
                      : g_x[((b * NHS + ch) * 6 + Y) * 6 + X];
        else if (ch < 66)
            v = cell[b * 2 + (ch - NHS)];
        else
            v = coord[((b * 2 + (ch - 66)) * 6 + Y) * 6 + X];
        sh_t[slot * NC * P + ch * P + p] = sc_act(v);
    }

    const int slot = tid & 3;
    const int co   = tid >> 2;
    float* tin = sh_t + slot * NC * P;

    float acc[P];
    {
        const float bb = b1[co];
        #pragma unroll
        for (int p = 0; p < P; p++) acc[p] = bb;
    }
    conv_accum<WS>(acc, w1, sh_w, tin, co, tid);

    // relu + sin+cos, write intermediate back into the same tile buffer
    __syncthreads();
    #pragma unroll
    for (int p = 0; p < P; p++)
        tin[co * P + p] = sc_act(fmaxf(acc[p], 0.f));
    // conv_accum's leading __syncthreads orders these writes before reads

    {
        const float bb = b3[co];
        #pragma unroll
        for (int p = 0; p < P; p++) acc[p] = bb;
    }
    conv_accum<WS>(acc, w3, sh_w, tin, co, tid);

    const int tile = tile0 + slot;
    float* outp = g_vec + (size_t)tile * (NC * P) + co * P;
    #pragma unroll
    for (int p = 0; p < P; p++) outp[p] = fmaxf(acc[p], 0.f);
}

// ---------------- SGEMM: out[m,n] = relu?(sum_k g_vec[m,k]*W[n,k] + bias[n]) -
// MODE 0: linear layer -> relu -> scatter into g_x (corner reassembly)
// MODE 1: final layer -> g_mat[m*64+n]
template<int MODE>
__global__ void __launch_bounds__(256) sgemm_kernel(
    const float* __restrict__ W,
    const float* __restrict__ bias,
    int K)
{
    __shared__ float As[16][64];
    __shared__ float Bs[16][64];
    const int m0  = blockIdx.x * 64;
    const int n0  = blockIdx.y * 64;
    const int tid = threadIdx.x;
    const int tx  = tid & 15, ty = tid >> 4;
    float acc[4][4] = {};
    const float* A = g_vec;

    for (int k0 = 0; k0 < K; k0 += 16) {
        #pragma unroll
        for (int i = 0; i < 4; i++) {
            const int idx = tid + 256 * i;
            const int mm = idx >> 4, kk = idx & 15;
            const bool ok = (k0 + kk) < K;
            As[kk][mm] = ok ? A[(size_t)(m0 + mm) * K + k0 + kk] : 0.f;
            Bs[kk][mm] = ok ? W[(size_t)(n0 + mm) * K + k0 + kk] : 0.f;
        }
        __syncthreads();
        #pragma unroll
        for (int kk = 0; kk < 16; kk++) {
            float a[4], b[4];
            #pragma unroll
            for (int i = 0; i < 4; i++) a[i] = As[kk][ty * 4 + i];
            #pragma unroll
            for (int j = 0; j < 4; j++) b[j] = Bs[kk][tx * 4 + j];
            #pragma unroll
            for (int i = 0; i < 4; i++)
                #pragma unroll
                for (int j = 0; j < 4; j++)
                    acc[i][j] = fmaf(a[i], b[j], acc[i][j]);
        }
        __syncthreads();
    }

    #pragma unroll
    for (int i = 0; i < 4; i++) {
        const int m = m0 + ty * 4 + i;
        const int c = m >> 13, b = m & (BATCH - 1);
        #pragma unroll
        for (int j = 0; j < 4; j++) {
            const int n = n0 + tx * 4 + j;
            float v = acc[i][j] + bias[n];
            if (MODE == 0) {
                v = fmaxf(v, 0.f);
                const int h = n / 9, r = (n % 9) / 3, cc = n % 3;
                g_x[((b * NHS + h) * 6 + r + 3 * (c >> 1)) * 6 + cc + 3 * (c & 1)] = v;
            } else {
                g_mat[m * NHS + n] = v;
            }
        }
    }
}

// gather the 4 exact 3x3 quadrants of x into g_vec rows of length 576
__global__ void extract_final_kernel() {
    const int idx = blockIdx.x * blockDim.x + threadIdx.x;
    if (idx >= 4 * BATCH * 576) return;
    const int m = idx / 576, k = idx % 576;
    const int c = m >> 13, b = m & (BATCH - 1);
    const int ch = k / 9, r = (k % 9) / 3, cc = k % 3;
    g_vec[idx] = g_x[((b * NHS + ch) * 6 + r + 3 * (c >> 1)) * 6 + cc + 3 * (c & 1)];
}

// out(b,h,i,j) = x[b,h,2+i,2+j] * matflat[b*256 + h*4 + i*2 + j]
// (the reference's (4B,64) -> (B,64,2,2) reshape is a flat reinterpretation,
//  and g_mat is stored in exactly that flat order)
__global__ void final_mul_kernel(float* __restrict__ out) {
    const int idx = blockIdx.x * blockDim.x + threadIdx.x;
    if (idx >= BATCH * NHS * 4) return;
    const int b = idx >> 8, rest = idx & 255;
    const int h = rest >> 2, ij = rest & 3;
    const float xc = g_x[((b * NHS + h) * 6 + 2 + (ij >> 1)) * 6 + 2 + (ij & 1)];
    out[idx] = xc * g_mat[idx];
}

extern "C" void kernel_launch(void* const* d_in, const int* in_sizes, int n_in,
                              void* d_out, int out_size)
{
    const float* x     = (const float*)d_in[0];
    const float* cell  = (const float*)d_in[1];
    const float* coord = (const float*)d_in[2];
    const float* c1w   = (const float*)d_in[3];
    const float* c1b   = (const float*)d_in[4];
    const float* c3w   = (const float*)d_in[5];
    const float* c3b   = (const float*)d_in[6];
    const float* l5w   = (const float*)d_in[7];
    const float* l5b   = (const float*)d_in[8];
    const float* l4w   = (const float*)d_in[9];
    const float* l4b   = (const float*)d_in[10];
    const float* l3w   = (const float*)d_in[11];
    const float* l3b   = (const float*)d_in[12];
    const float* fw    = (const float*)d_in[13];
    const float* fb    = (const float*)d_in[14];
    float* out = (float*)d_out;

    // ws = 5
    conv_pipe<5, true ><<<BATCH, 272>>>(x, cell, coord, c1w, c1b, c3w, c3b);
    sgemm_kernel<0><<<dim3(512, 9), 256>>>(l5w, l5b, NC * 25);
    // ws = 4
    conv_pipe<4, false><<<BATCH, 272>>>(x, cell, coord, c1w, c1b, c3w, c3b);
    sgemm_kernel<0><<<dim3(512, 9), 256>>>(l4w, l4b, NC * 16);
    // ws = 3
    conv_pipe<3, false><<<BATCH, 272>>>(x, cell, coord, c1w, c1b, c3w, c3b);
    sgemm_kernel<0><<<dim3(512, 9), 256>>>(l3w, l3b, NC * 9);
    // final
    extract_final_kernel<<<(4 * BATCH * 576 + 255) / 256, 256>>>();
    sgemm_kernel<1><<<dim3(512, 1), 256>>>(fw, fb, 576);
    final_mul_kernel<<<(BATCH * NHS * 4 + 255) / 256, 256>>>(out);
}

// round 2
// speedup vs baseline: 1.1264x; 1.1264x over previous
#include <cuda_runtime.h>
#include <math.h>

#define BATCH 8192
#define NHS   64
#define NC    68   // HS + 4 channels

typedef unsigned long long ull;

// ---------------- scratch (device globals: no allocation allowed) ----------
__device__ float g_x[BATCH * NHS * 36];            // current x, (B,64,6,6)
__device__ float g_vec[4 * BATCH * NC * 25];       // conv output vectors
__device__ float g_mat[4 * BATCH * NHS];           // final matmul result

// ---------------- f32x2 packed helpers --------------------------------------
__device__ __forceinline__ ull ffma2(ull a, ull b, ull c) {
    ull d;
    asm("fma.rn.f32x2 %0, %1, %2, %3;" : "=l"(d) : "l"(a), "l"(b), "l"(c));
    return d;
}
__device__ __forceinline__ ull pack2(float lo, float hi) {
    ull d;
    asm("mov.b64 %0, {%1, %2};" : "=l"(d) : "f"(lo), "f"(hi));
    return d;
}
__device__ __forceinline__ void unpack2(ull v, float& lo, float& hi) {
    asm("mov.b64 {%0, %1}, %2;" : "=f"(lo), "=f"(hi) : "l"(v));
}

__device__ __forceinline__ float sc_act(float v) {
    return __sinf(v) + __cosf(v);
}

// ---------------- conv core: one 3x3 SAME conv, channel-paired f32x2 --------
// Thread owns one (co-pair, slot). Weights staged in shared as interleaved
// channel pairs (LDS.64 -> pair), inputs stored duplicated (LDS.64 -> broadcast).
template<int WS>
__device__ __forceinline__ void conv_core(
    ull* acc, const float* __restrict__ wg,
    float* sh_w, const float* tin, int cop, int tid)
{
    constexpr int P = WS * WS;
    #pragma unroll 1
    for (int chunk = 0; chunk < 17; chunk++) {
        __syncthreads();
        // stage w pairs: layout [c2(34)][cil(4)][k(9)][pc(2)]
        for (int e = tid; e < 34 * 4 * 9 * 2; e += 272) {
            const int pc = e & 1;
            const int t  = e >> 1;
            const int k  = t % 9;
            const int t2 = t / 9;
            const int cil = t2 & 3;
            const int c2  = t2 >> 2;
            sh_w[e] = wg[(c2 * 2 + pc) * 612 + (chunk * 4 + cil) * 9 + k];
        }
        __syncthreads();
        #pragma unroll
        for (int cil = 0; cil < 4; cil++) {
            const int ci = chunk * 4 + cil;
            ull r2[P];
            #pragma unroll
            for (int p = 0; p < P; p++)
                r2[p] = *(const ull*)&tin[(ci * P + p) * 2];
            ull wv[9];
            #pragma unroll
            for (int k = 0; k < 9; k++)
                wv[k] = *(const ull*)&sh_w[cop * 72 + cil * 18 + k * 2];
            #pragma unroll
            for (int y = 0; y < WS; y++) {
                #pragma unroll
                for (int x = 0; x < WS; x++) {
                    ull a = acc[y * WS + x];
                    #pragma unroll
                    for (int ky = 0; ky < 3; ky++) {
                        const int yy = y + ky - 1;
                        if (yy < 0 || yy >= WS) continue;
                        #pragma unroll
                        for (int kx = 0; kx < 3; kx++) {
                            const int xx = x + kx - 1;
                            if (xx < 0 || xx >= WS) continue;
                            a = ffma2(wv[ky * 3 + kx], r2[yy * WS + xx], a);
                        }
                    }
                    acc[y * WS + x] = a;
                }
            }
        }
    }
}

// ---------------- fused per-iteration conv pipeline -------------------------
// One CTA = 8 (corner,batch) tiles. 272 threads: cop = tid>>3 (0..33), slot = tid&7.
template<int WS, bool FIRST>
__global__ void __launch_bounds__(272, 1) conv_pipe(
    const float* __restrict__ xin,
    const float* __restrict__ cell,
    const float* __restrict__ coord,
    const float* __restrict__ w1, const float* __restrict__ b1,
    const float* __restrict__ w3, const float* __restrict__ b3)
{
    constexpr int P    = WS * WS;
    constexpr int OFF  = 6 - WS;
    constexpr int TSTR = NC * P * 2 + 4;   // floats per slot (padded, bank-spread)
    extern __shared__ float sh[];
    float* sh_t = sh;                // 8 * TSTR floats (duplicated tiles)
    float* sh_w = sh + 8 * TSTR;     // 2448 floats

    const int tid   = threadIdx.x;
    const int slot  = tid & 7;
    const int cop   = tid >> 3;
    const int tile0 = blockIdx.x * 8;

    // corner-extract + concat + sin+cos, stored duplicated
    for (int e = tid; e < 8 * NC * P; e += 272) {
        const int s  = e / (NC * P);
        const int rr = e % (NC * P);
        const int ch = rr / P, p = rr % P;
        const int y  = p / WS, xp = p % WS;
        const int tile = tile0 + s;
        const int c = tile >> 13, b = tile & (BATCH - 1);
        const int Y = y + (c >> 1) * OFF, X = xp + (c & 1) * OFF;
        float v;
        if (ch < NHS)
            v = FIRST ? xin[((b * NHS + ch) * 6 + Y) * 6 + X]
                      : g_x[((b * NHS + ch) * 6 + Y) * 6 + X];
        else if (ch < 66)
            v = cell[b * 2 + (ch - NHS)];
        else
            v = coord[((b * 2 + (ch - 66)) * 6 + Y) * 6 + X];
        const float a = sc_act(v);
        sh_t[s * TSTR + rr * 2]     = a;
        sh_t[s * TSTR + rr * 2 + 1] = a;
    }

    float* tin = sh_t + slot * TSTR;

    ull acc[P];
    {
        const float2 bb = *(const float2*)&b1[2 * cop];
        const ull bi = pack2(bb.x, bb.y);
        #pragma unroll
        for (int p = 0; p < P; p++) acc[p] = bi;
    }
    conv_core<WS>(acc, w1, sh_w, tin, cop, tid);

    // relu + act, write back duplicated (sync first: others may still read)
    __syncthreads();
    #pragma unroll
    for (int p = 0; p < P; p++) {
        float lo, hi;
        unpack2(acc[p], lo, hi);
        const float alo = sc_act(fmaxf(lo, 0.f));
        const float ahi = sc_act(fmaxf(hi, 0.f));
        tin[((2 * cop)     * P + p) * 2]     = alo;
        tin[((2 * cop)     * P + p) * 2 + 1] = alo;
        tin[((2 * cop + 1) * P + p) * 2]     = ahi;
        tin[((2 * cop + 1) * P + p) * 2 + 1] = ahi;
    }
    // conv_core's leading __syncthreads orders these writes before reads

    {
        const float2 bb = *(const float2*)&b3[2 * cop];
        const ull bi = pack2(bb.x, bb.y);
        #pragma unroll
        for (int p = 0; p < P; p++) acc[p] = bi;
    }
    conv_core<WS>(acc, w3, sh_w, tin, cop, tid);

    const int tile = tile0 + slot;
    float* outp = g_vec + (size_t)tile * (NC * P);
    #pragma unroll
    for (int p = 0; p < P; p++) {
        float lo, hi;
        unpack2(acc[p], lo, hi);
        outp[(2 * cop)     * P + p] = fmaxf(lo, 0.f);
        outp[(2 * cop + 1) * P + p] = fmaxf(hi, 0.f);
    }
}

// ---------------- f32x2 SGEMM: 128x128 block, 8x8 microtile -----------------
// acc pairs along m (LDS.64 from As); b broadcast packed via ALU movs.
// MODE 0: +bias, relu, scatter into g_x. MODE 1: +bias -> g_mat.
template<int MODE>
__global__ void __launch_bounds__(256) sgemm2(
    const float* __restrict__ Wt,
    const float* __restrict__ bias,
    int K, int Ntot)
{
    __shared__ float As[16][128];
    __shared__ float Bs[16][128];
    const int tid = threadIdx.x;
    const int tx  = tid & 15;        // n direction (strided n = tx + j*16)
    const int ty  = tid >> 4;        // m direction (m = ty*8 + 0..7)
    const int n0  = blockIdx.x * 128;
    const int m0  = blockIdx.y * 128;
    const float* A = g_vec;

    ull acc[4][8];
    #pragma unroll
    for (int ip = 0; ip < 4; ip++)
        #pragma unroll
        for (int j = 0; j < 8; j++) acc[ip][j] = 0ull;

    for (int k0 = 0; k0 < K; k0 += 16) {
        #pragma unroll
        for (int i = 0; i < 2; i++) {
            const int q   = tid + 256 * i;
            const int row = q >> 2, kq = q & 3;
            const int kg  = k0 + kq * 4;
            float4 va = make_float4(0.f, 0.f, 0.f, 0.f);
            float4 vb = va;
            if (kg < K) {
                va = *(const float4*)&A[(size_t)(m0 + row) * K + kg];
                if (n0 + row < Ntot)
                    vb = *(const float4*)&Wt[(size_t)(n0 + row) * K + kg];
            }
            As[kq * 4 + 0][row] = va.x; As[kq * 4 + 1][row] = va.y;
            As[kq * 4 + 2][row] = va.z; As[kq * 4 + 3][row] = va.w;
            Bs[kq * 4 + 0][row] = vb.x; Bs[kq * 4 + 1][row] = vb.y;
            Bs[kq * 4 + 2][row] = vb.z; Bs[kq * 4 + 3][row] = vb.w;
        }
        __syncthreads();
        #pragma unroll
        for (int kk = 0; kk < 16; kk++) {
            ull a[4], b2[8];
            #pragma unroll
            for (int ip = 0; ip < 4; ip++)
                a[ip] = *(const ull*)&As[kk][ty * 8 + ip * 2];
            #pragma unroll
            for (int j = 0; j < 8; j++) {
                const float bv = Bs[kk][tx + j * 16];
                b2[j] = pack2(bv, bv);
            }
            #pragma unroll
            for (int ip = 0; ip < 4; ip++)
                #pragma unroll
                for (int j = 0; j < 8; j++)
                    acc[ip][j] = ffma2(a[ip], b2[j], acc[ip][j]);
        }
        __syncthreads();
    }

    #pragma unroll
    for (int j = 0; j < 8; j++) {
        const int n = n0 + tx + j * 16;
        if (n >= Ntot) continue;
        const float bb = bias[n];
        #pragma unroll
        for (int ip = 0; ip < 4; ip++) {
            float lo, hi;
            unpack2(acc[ip][j], lo, hi);
            const int m = m0 + ty * 8 + ip * 2;
            if (MODE == 0) {
                const int h = n / 9, r = (n % 9) / 3, cc = n % 3;
                {
                    const int c = m >> 13, b = m & (BATCH - 1);
                    g_x[((b * NHS + h) * 6 + r + 3 * (c >> 1)) * 6 + cc + 3 * (c & 1)]
                        = fmaxf(lo + bb, 0.f);
                }
                {
                    const int m1 = m + 1;
                    const int c = m1 >> 13, b = m1 & (BATCH - 1);
                    g_x[((b * NHS + h) * 6 + r + 3 * (c >> 1)) * 6 + cc + 3 * (c & 1)]
                        = fmaxf(hi + bb, 0.f);
                }
            } else {
                g_mat[m * NHS + n]       = lo + bb;
                g_mat[(m + 1) * NHS + n] = hi + bb;
            }
        }
    }
}

// gather the 4 exact 3x3 quadrants of x into g_vec rows of length 576
__global__ void extract_final_kernel() {
    const int idx = blockIdx.x * blockDim.x + threadIdx.x;
    if (idx >= 4 * BATCH * 576) return;
    const int m = idx / 576, k = idx % 576;
    const int c = m >> 13, b = m & (BATCH - 1);
    const int ch = k / 9, r = (k % 9) / 3, cc = k % 3;
    g_vec[idx] = g_x[((b * NHS + ch) * 6 + r + 3 * (c >> 1)) * 6 + cc + 3 * (c & 1)];
}

// out = x_center * g_mat (flat reinterpretation of the (4B,64)->(B,64,2,2) reshape)
__global__ void final_mul_kernel(float* __restrict__ out) {
    const int idx = blockIdx.x * blockDim.x + threadIdx.x;
    if (idx >= BATCH * NHS * 4) return;
    const int b = idx >> 8, rest = idx & 255;
    const int h = rest >> 2, ij = rest & 3;
    const float xc = g_x[((b * NHS + h) * 6 + 2 + (ij >> 1)) * 6 + 2 + (ij & 1)];
    out[idx] = xc * g_mat[idx];
}

extern "C" void kernel_launch(void* const* d_in, const int* in_sizes, int n_in,
                              void* d_out, int out_size)
{
    const float* x     = (const float*)d_in[0];
    const float* cell  = (const float*)d_in[1];
    const float* coord = (const float*)d_in[2];
    const float* c1w   = (const float*)d_in[3];
    const float* c1b   = (const float*)d_in[4];
    const float* c3w   = (const float*)d_in[5];
    const float* c3b   = (const float*)d_in[6];
    const float* l5w   = (const float*)d_in[7];
    const float* l5b   = (const float*)d_in[8];
    const float* l4w   = (const float*)d_in[9];
    const float* l4b   = (const float*)d_in[10];
    const float* l3w   = (const float*)d_in[11];
    const float* l3b   = (const float*)d_in[12];
    const float* fw    = (const float*)d_in[13];
    const float* fb    = (const float*)d_in[14];
    float* out = (float*)d_out;

    const int sh5 = (8 * (NC * 25 * 2 + 4) + 2448) * 4;   // 118720 B
    const int sh4 = (8 * (NC * 16 * 2 + 4) + 2448) * 4;   // 79552 B
    const int sh3 = (8 * (NC * 9 * 2 + 4) + 2448) * 4;    // 49088 B
    cudaFuncSetAttribute(conv_pipe<5, true >, cudaFuncAttributeMaxDynamicSharedMemorySize, sh5);
    cudaFuncSetAttribute(conv_pipe<4, false>, cudaFuncAttributeMaxDynamicSharedMemorySize, sh4);
    cudaFuncSetAttribute(conv_pipe<3, false>, cudaFuncAttributeMaxDynamicSharedMemorySize, sh3);

    const int NCONV = BATCH * 4 / 8;   // 4096 CTAs

    // ws = 5
    conv_pipe<5, true ><<<NCONV, 272, sh5>>>(x, cell, coord, c1w, c1b, c3w, c3b);
    sgemm2<0><<<dim3(5, 256), 256>>>(l5w, l5b, NC * 25, 576);
    // ws = 4
    conv_pipe<4, false><<<NCONV, 272, sh4>>>(x, cell, coord, c1w, c1b, c3w, c3b);
    sgemm2<0><<<dim3(5, 256), 256>>>(l4w, l4b, NC * 16, 576);
    // ws = 3
    conv_pipe<3, false><<<NCONV, 272, sh3>>>(x, cell, coord, c1w, c1b, c3w, c3b);
    sgemm2<0><<<dim3(5, 256), 256>>>(l3w, l3b, NC * 9, 576);
    // final
    extract_final_kernel<<<(4 * BATCH * 576 + 255) / 256, 256>>>();
    sgemm2<1><<<dim3(1, 256), 256>>>(fw, fb, 576, NHS);
    final_mul_kernel<<<(BATCH * NHS * 4 + 255) / 256, 256>>>(out);
}